// round 9
// baseline (speedup 1.0000x reference)
#include <cuda_runtime.h>
#include <stdint.h>
#include <stddef.h>

// Problem constants
#define BB 8
#define CC 64
#define MM 4
#define NN 400
#define TT 24
#define QQ 8
#define PP (MM*NN*TT)        // 38400 columns per batch
#define BNM (BB*NN*MM)       // 12800
#define MASK_NUM 1280        // int(12800*0.1)

typedef unsigned long long ull;

// -------- device scratch (no allocations allowed) --------
__device__ float g_w[BNM];          // w = 1 - sim, flattened (b,n,m)
__device__ float g_levels[25600];   // associative-scan level storage
__device__ float g_scans[25600];    // associative-scan results per level
__device__ int   g_midx[MASK_NUM];  // sampled indices
__device__ float g_Tp[CC*TT];
__device__ float g_Sp[CC*NN];
__device__ float g_Mp[CC*MM];       // includes proj_b folded in

// ============================================================
// forced 4-byte global accesses (no vector merging, L1-cacheable)
// ============================================================
__device__ __forceinline__ float ldg32(const float* p) {
    float v; asm volatile("ld.global.f32 %0, [%1];" : "=f"(v) : "l"(p)); return v;
}
__device__ __forceinline__ void stg32(float* p, float v) {
    asm volatile("st.global.f32 [%0], %1;" :: "l"(p), "f"(v));
}

// ============================================================
// tf32 round (cvt.rna) — returns the tf32 value as an f32
// ============================================================
__device__ __forceinline__ float tf32r(float x) {
    uint32_t u;
    asm("cvt.rna.tf32.f32 %0, %1;" : "=r"(u) : "f"(x));
    return __uint_as_float(u);
}

// m16n8k8 tf32 MMA, fp32 accumulate
#define MMA_TF32(d, a0,a1,a2,a3, b0,b1) \
    asm volatile("mma.sync.aligned.m16n8k8.row.col.f32.tf32.tf32.f32 " \
        "{%0,%1,%2,%3}, {%4,%5,%6,%7}, {%8,%9}, {%0,%1,%2,%3};" \
        : "+f"(d[0]), "+f"(d[1]), "+f"(d[2]), "+f"(d[3]) \
        : "r"(__float_as_uint(a0)), "r"(__float_as_uint(a1)), \
          "r"(__float_as_uint(a2)), "r"(__float_as_uint(a3)), \
          "r"(__float_as_uint(b0)), "r"(__float_as_uint(b1)))

// ============================================================
// XLA:CPU exp (GenerateVF32Exp / Cephes pexp, UNFUSED mul+add)
// ============================================================
__device__ __forceinline__ float xla_exp(float input) {
    float x = fminf(input, 88.3762626647950f);
    x = fmaxf(x, -88.3762626647949f);
    float fx = __fadd_rn(__fmul_rn(x, 1.44269504088896341f), 0.5f);
    fx = floorf(fx);
    float tmp = __fmul_rn(fx, 0.693359375f);
    float z   = __fmul_rn(fx, -2.12194440e-4f);
    x = __fsub_rn(x, tmp);
    x = __fsub_rn(x, z);
    z = __fmul_rn(x, x);
    float y = 1.9875691500E-4f;
    y = __fadd_rn(__fmul_rn(y, x), 1.3981999507E-3f);
    y = __fadd_rn(__fmul_rn(y, x), 8.3334519073E-3f);
    y = __fadd_rn(__fmul_rn(y, x), 4.1665795894E-2f);
    y = __fadd_rn(__fmul_rn(y, x), 1.6666665459E-1f);
    y = __fadd_rn(__fmul_rn(y, x), 5.0000001201E-1f);
    y = __fadd_rn(__fmul_rn(y, z), x);
    y = __fadd_rn(y, 1.0f);
    int emm0 = (int)fx;
    emm0 = (emm0 + 0x7f) << 23;
    return __fmul_rn(y, __int_as_float(emm0));
}

// ============================================================
// threefry2x32-20, key = PRNGKey(42) = (0, 42)
// ============================================================
__device__ __forceinline__ uint32_t rotl32(uint32_t x, int r) {
    return (x << r) | (x >> (32 - r));
}
__device__ void threefry2x32(uint32_t c0, uint32_t c1, uint32_t& o0, uint32_t& o1) {
    const uint32_t k0 = 0u, k1 = 42u;
    uint32_t ks[3] = {k0, k1, 0x1BD11BDAu ^ k0 ^ k1};
    uint32_t x0 = c0 + ks[0];
    uint32_t x1 = c1 + ks[1];
    const int rotA[4] = {13,15,26,6};
    const int rotB[4] = {17,29,16,24};
#pragma unroll
    for (int i = 0; i < 5; i++) {
#pragma unroll
        for (int j = 0; j < 4; j++) {
            int r = (i & 1) ? rotB[j] : rotA[j];
            x0 += x1;
            x1 = rotl32(x1, r);
            x1 ^= x0;
        }
        x0 += ks[(i + 1) % 3];
        x1 += ks[(i + 2) % 3] + (uint32_t)(i + 1);
    }
    o0 = x0; o1 = x1;
}

// ============================================================
// k_pre: blocks 0..199 -> sim/w (coalesced); blocks 200..306 -> Tp/Sp/Mp
// (bit-exact proven in R7/R8: fingerprint 2.070723e-07)
// ============================================================
__global__ void __launch_bounds__(256) k_pre(
    const float* __restrict__ rep,
    const float* __restrict__ att_w,
    const float* __restrict__ att_b,
    const float* __restrict__ temb,
    const float* __restrict__ semb,
    const float* __restrict__ memb,
    const float* __restrict__ proj_w,
    const float* __restrict__ proj_b)
{
    const int bid = blockIdx.x;
    const int tid = threadIdx.x;

    if (bid >= 200) {   // ---- embedding projections ----
        const int idx = (bid - 200) * 256 + tid;
        const int total = CC * (TT + NN + MM);
        if (idx >= total) return;
        const int o = idx / (TT + NN + MM);
        const int j = idx % (TT + NN + MM);
        const float* w2 = proj_w + o*2*CC + CC;   // W2[o][c] = proj_w[o,64+c]
        float acc = 0.f;
        if (j < TT) {
#pragma unroll 8
            for (int c = 0; c < CC; c++) acc = fmaf(w2[c], temb[c*TT + j], acc);
            g_Tp[o*TT + j] = acc;
        } else if (j < TT + NN) {
            const int n = j - TT;
#pragma unroll 8
            for (int c = 0; c < CC; c++) acc = fmaf(w2[c], semb[c*NN + n], acc);
            g_Sp[o*NN + n] = acc;
        } else {
            const int m = j - TT - NN;
#pragma unroll 8
            for (int c = 0; c < CC; c++) acc = fmaf(w2[c], memb[c*MM + m], acc);
            g_Mp[o*MM + m] = acc + proj_b[o];
        }
        return;
    }

    // ---- sim: block = (b, 16 n's); coalesced tile staging ----
    __shared__ float tile[CC*MM][17];   // [e=c*4+m][j]
    __shared__ float aw[QQ*CC];
    __shared__ float pm_s[QQ][16][4];
    const int b  = bid / 25;
    const int n0 = (bid % 25) * 16;

    for (int i = tid; i < QQ*CC; i += 256) aw[i] = att_w[i];
    const float* repb = rep + (size_t)b * CC * MM * NN + n0;
    for (int idx = tid; idx < CC*MM*16; idx += 256) {
        int e = idx >> 4, j = idx & 15;
        tile[e][j] = repb[(size_t)e * NN + j];
    }
    __syncthreads();

    if (tid < 128) {
        const int q = tid >> 4, j = tid & 15;
        float A[4];
#pragma unroll
        for (int m = 0; m < 4; m++) {
            float acc = 0.f;   // ascending-c single fma chain (frozen order)
#pragma unroll 8
            for (int c = 0; c < CC; c++)
                acc = fmaf(tile[c*4 + m][j], aw[q*CC + c], acc);
            A[m] = __fadd_rn(acc, att_b[q]);
        }
        float mx = fmaxf(fmaxf(fmaxf(A[0], A[1]), A[2]), A[3]);
        float e[4];
#pragma unroll
        for (int m = 0; m < 4; m++) e[m] = xla_exp(__fsub_rn(A[m], mx));
        float s = __fadd_rn(__fadd_rn(__fadd_rn(e[0], e[1]), e[2]), e[3]);
#pragma unroll
        for (int m = 0; m < 4; m++) pm_s[q][j][m] = __fdiv_rn(e[m], s);
    }
    __syncthreads();

    if (tid < 64) {
        const int j = tid >> 2, m = tid & 3;
        float sumq = 0.f;
#pragma unroll
        for (int q = 0; q < 8; q++) sumq = __fadd_rn(sumq, pm_s[q][j][m]);
        float sim = __fmul_rn(sumq, 0.125f);
        g_w[(b*NN + n0 + j)*MM + m] = __fsub_rn(1.0f, sim);
    }
}

// ============================================================
// mask pipeline (block 0 of merged kernel, 256 threads)
// bit-exact proven (R7/R8 fingerprint)
// ============================================================
__device__ void mask_work() {
    const int tid = threadIdx.x;
    __shared__ float S_sh;
    __shared__ float lane_sums[4];
    const int sizes[14] = {12800,6400,3200,1600,800,400,200,100,50,25,12,6,3,1};
    int offs[14];
    { int o = 0; for (int k = 0; k < 14; k++) { offs[k] = o; o += sizes[k]; } }

    // ---- S = sum(w): XLA:CPU EmitVectorizedReduce, NEON 4-lane ----
    if (tid < 4) {
        float a = 0.f;
#pragma unroll 8
        for (int j = 0; j < BNM/4; j++)
            a = __fadd_rn(a, ldg32(&g_w[4*j + tid]));
        lane_sums[tid] = a;
    }
    __syncthreads();
    if (tid == 0) {
        float lo = __fadd_rn(lane_sums[0], lane_sums[2]);
        float hi = __fadd_rn(lane_sums[1], lane_sums[3]);
        S_sh = __fadd_rn(lo, hi);
    }
    __syncthreads();
    const float S = S_sh;

    // ---- level 0: p = w / S ----
    for (int i = tid; i < BNM; i += 256)
        stg32(&g_levels[i], __fdiv_rn(ldg32(&g_w[i]), S));
    __syncthreads();

    // ---- down-sweep ----
    for (int k = 0; k < 13; k++) {
        const int so = offs[k], dofs = offs[k+1];
        const int nk1 = sizes[k+1];
        for (int i = tid; i < nk1; i += 256) {
            float a  = ldg32(&g_levels[so + 2*i]);
            float b2 = ldg32(&g_levels[so + 2*i + 1]);
            stg32(&g_levels[dofs + i], __fadd_rn(a, b2));
        }
        __syncthreads();
    }
    // ---- up-sweep: jax associative_scan interleave ----
    if (tid == 0) stg32(&g_scans[offs[13]], ldg32(&g_levels[offs[13]]));
    __syncthreads();
    for (int k = 12; k >= 0; k--) {
        const int lo_ = offs[k], ho = offs[k+1];
        const int nk = sizes[k], nk1 = sizes[k+1];
        if (tid == 0) stg32(&g_scans[lo_], ldg32(&g_levels[lo_]));
        for (int i = tid; i < nk1; i += 256) {
            float sv = ldg32(&g_scans[ho + i]);
            stg32(&g_scans[lo_ + 2*i + 1], sv);
            if (2*i + 2 < nk)
                stg32(&g_scans[lo_ + 2*i + 2],
                      __fadd_rn(sv, ldg32(&g_levels[lo_ + 2*i + 2])));
        }
        __syncthreads();
    }
    const float plast = ldg32(&g_scans[BNM - 1]);

    // ---- sample 1280 indices (jax searchsorted method='scan'), 5-wide ILP ----
    float rr[5]; int lo5[5], hi5[5];
#pragma unroll
    for (int s = 0; s < 5; s++) {
        int k = tid + s*256;
        uint32_t o0, o1;
        threefry2x32(0u, (uint32_t)k, o0, o1);   // partitionable mode
        uint32_t bits = o0 ^ o1;
        float u = __fsub_rn(__uint_as_float((bits >> 9) | 0x3f800000u), 1.0f);
        rr[s] = __fmul_rn(plast, __fsub_rn(1.0f, u));
        lo5[s] = 0; hi5[s] = BNM;
    }
#pragma unroll
    for (int it = 0; it < 14; it++) {            // ceil(log2(12801)) = 14
#pragma unroll
        for (int s = 0; s < 5; s++) {
            int mid = (lo5[s] + hi5[s]) >> 1;
            float v = g_scans[mid];
            if (rr[s] <= v) hi5[s] = mid; else lo5[s] = mid;
        }
    }
#pragma unroll
    for (int s = 0; s < 5; s++) g_midx[tid + s*256] = hi5[s];
}

// ============================================================
// Merged kernel: block 0 = mask pipeline; blocks 1..2400 = tf32-3x GEMM
// Tile: 64 o x 128 p per block; 8 warps, each 16 p x 64 o.
// mma.sync.m16n8k8 tf32: A = X^T (m=p, k=c), B = W1 (k=c, n=o).
// D = Xhi*Whi + Xhi*Wlo + Xlo*Whi  (fp32 accumulate)
// smem: Xhi/Xlo [64][136], Whi/Wlo [64][68], Tp/Sp/Mp tables
// ============================================================
#define XROW 136
#define WROWF 68
#define SM_XHI 0
#define SM_XLO (CC*XROW)
#define SM_WHI (2*CC*XROW)
#define SM_WLO (2*CC*XROW + CC*WROWF)
#define SM_TPS (2*CC*XROW + 2*CC*WROWF)
#define SM_SPS (SM_TPS + CC*TT)
#define SM_MPS (SM_SPS + CC*8)
#define SMEM_FLOATS (SM_MPS + CC)
#define SMEM_BYTES (SMEM_FLOATS * 4)

__global__ void __launch_bounds__(256) k_merged(const float* __restrict__ x,
                                                const float* __restrict__ proj_w,
                                                float* __restrict__ out) {
    extern __shared__ __align__(16) float dsm[];

    if (blockIdx.x == 0) { mask_work(); return; }

    float* Xhi = dsm + SM_XHI;
    float* Xlo = dsm + SM_XLO;
    float* Whi = dsm + SM_WHI;
    float* Wlo = dsm + SM_WLO;
    float* Tps = dsm + SM_TPS;
    float* Sps = dsm + SM_SPS;
    float* Mps = dsm + SM_MPS;

    const int g_   = blockIdx.x - 1;
    const int b    = g_ / 300;
    const int p0   = (g_ % 300) * 128;
    const int tid  = threadIdx.x;
    const int wid  = tid >> 5;
    const int lane = tid & 31;
    const int gq   = lane >> 2;       // groupID 0..7
    const int tg   = lane & 3;        // threadID_in_group 0..3

    const int m     = p0 / 9600;
    const int nbase = (p0 % 9600) / 24;

    // ---- stage W split: Whi/Wlo[o][c], row WROWF ----
    for (int i = tid; i < CC*CC; i += 256) {
        int o = i >> 6, c = i & 63;
        float w = proj_w[o*2*CC + c];
        float h = tf32r(w);
        Whi[o*WROWF + c] = h;
        Wlo[o*WROWF + c] = tf32r(__fsub_rn(w, h));
    }
    // ---- stage epilogue tables ----
    for (int i = tid; i < CC*TT; i += 256) Tps[i] = g_Tp[i];
    for (int i = tid; i < CC*8; i += 256) {
        int o = i >> 3, nn = i & 7;
        int n = nbase + nn;
        Sps[i] = (n < NN) ? g_Sp[o*NN + n] : 0.f;
    }
    if (tid < CC) Mps[tid] = g_Mp[tid*MM + m];
    // ---- stage X split: Xhi/Xlo[c][p_local], row XROW ----
    const size_t xbase = (size_t)b * CC * PP + p0;
#pragma unroll
    for (int it = 0; it < 8; it++) {
        int idx = it*256 + tid;
        int cc = idx >> 5, p4 = idx & 31;
        float4 xv = *(const float4*)(x + xbase + (size_t)cc*PP + p4*4);
        int base = cc*XROW + p4*4;
        float h0 = tf32r(xv.x), h1 = tf32r(xv.y), h2 = tf32r(xv.z), h3 = tf32r(xv.w);
        Xhi[base+0] = h0; Xhi[base+1] = h1; Xhi[base+2] = h2; Xhi[base+3] = h3;
        Xlo[base+0] = tf32r(__fsub_rn(xv.x, h0));
        Xlo[base+1] = tf32r(__fsub_rn(xv.y, h1));
        Xlo[base+2] = tf32r(__fsub_rn(xv.z, h2));
        Xlo[base+3] = tf32r(__fsub_rn(xv.w, h3));
    }
    __syncthreads();

    // ---- main MMA loop ----
    float acc[8][4];
#pragma unroll
    for (int nt = 0; nt < 8; nt++)
#pragma unroll
        for (int j = 0; j < 4; j++) acc[nt][j] = 0.f;

    const int colA = wid*16 + gq;

#pragma unroll 2
    for (int k0 = 0; k0 < CC; k0 += 8) {
        const int r0 = (k0 + tg)*XROW;
        const int r1 = (k0 + tg + 4)*XROW;
        // A fragments (m16n8k8 tf32): a0=[g][tg] a1=[g+8][tg] a2=[g][tg+4] a3=[g+8][tg+4]
        float ah0 = Xhi[r0 + colA],     ah1 = Xhi[r0 + colA + 8];
        float ah2 = Xhi[r1 + colA],     ah3 = Xhi[r1 + colA + 8];
        float al0 = Xlo[r0 + colA],     al1 = Xlo[r0 + colA + 8];
        float al2 = Xlo[r1 + colA],     al3 = Xlo[r1 + colA + 8];
#pragma unroll
        for (int nt = 0; nt < 8; nt++) {
            // B fragments: b0=B[tg][g]=W[o=nt*8+g][c=k0+tg], b1=W[...][c=k0+tg+4]
            int wb = (nt*8 + gq)*WROWF + k0 + tg;
            float bh0 = Whi[wb], bh1 = Whi[wb + 4];
            float bl0 = Wlo[wb], bl1 = Wlo[wb + 4];
            MMA_TF32(acc[nt], ah0, ah1, ah2, ah3, bh0, bh1);
            MMA_TF32(acc[nt], ah0, ah1, ah2, ah3, bl0, bl1);
            MMA_TF32(acc[nt], al0, al1, al2, al3, bh0, bh1);
        }
    }

    // ---- epilogue ----
    // D layout: c0=[g][2tg] c1=[g][2tg+1] c2=[g+8][2tg] c3=[g+8][2tg+1]
    // row = p-local (colA, colA+8), col = o-local (nt*8 + 2tg, +1)
    const int pA = p0 + colA;
    const int pB = pA + 8;
    const int tA = pA % 24, tB = pB % 24;
    const int nnA = (pA % 9600)/24 - nbase;
    const int nnB = (pB % 9600)/24 - nbase;
#pragma unroll
    for (int nt = 0; nt < 8; nt++) {
        const int o0 = nt*8 + 2*tg;
        const int o1 = o0 + 1;
        float e0A = Tps[o0*TT + tA] + Sps[o0*8 + nnA] + Mps[o0];
        float e1A = Tps[o1*TT + tA] + Sps[o1*8 + nnA] + Mps[o1];
        float e0B = Tps[o0*TT + tB] + Sps[o0*8 + nnB] + Mps[o0];
        float e1B = Tps[o1*TT + tB] + Sps[o1*8 + nnB] + Mps[o1];
        float* r0 = out + (size_t)(b*CC + o0)*PP;
        float* r1 = out + (size_t)(b*CC + o1)*PP;
        r0[pA] = fmaxf(acc[nt][0] + e0A, 0.f);
        r1[pA] = fmaxf(acc[nt][1] + e1A, 0.f);
        r0[pB] = fmaxf(acc[nt][2] + e0B, 0.f);
        r1[pB] = fmaxf(acc[nt][3] + e1B, 0.f);
    }
}

// ============================================================
// k_fix: overwrite the 1280 masked (b,n,m) slices with relu(emb only)
// ============================================================
__global__ void __launch_bounds__(256) k_fix(float* __restrict__ out) {
    const int idx = g_midx[blockIdx.x];
    const int b = idx / (NN*MM);
    const int rr = idx % (NN*MM);
    const int n = rr >> 2;
    const int m = rr & 3;
    const int tid = threadIdx.x;
#pragma unroll
    for (int j = 0; j < 6; j++) {
        int i = j*256 + tid;           // i in [0,1536): o = i/24, t = i%24
        int o = i / 24;
        int t = i % 24;
        float v = g_Tp[o*TT + t] + g_Sp[o*NN + n] + g_Mp[o*MM + m];
        out[((size_t)(b*CC + o)*MM + m)*NN*TT + n*TT + t] = fmaxf(v, 0.0f);
    }
}

// ============================================================
extern "C" void kernel_launch(void* const* d_in, const int* in_sizes, int n_in,
                              void* d_out, int out_size) {
    const float* x      = (const float*)d_in[0];
    const float* rep    = (const float*)d_in[1];
    const float* att_w  = (const float*)d_in[2];
    const float* att_b  = (const float*)d_in[3];
    const float* temb   = (const float*)d_in[4];
    const float* semb   = (const float*)d_in[5];
    const float* memb   = (const float*)d_in[6];
    const float* proj_w = (const float*)d_in[7];
    const float* proj_b = (const float*)d_in[8];
    float* out = (float*)d_out;

    cudaFuncSetAttribute(k_merged, cudaFuncAttributeMaxDynamicSharedMemorySize,
                         SMEM_BYTES);

    k_pre<<<307, 256>>>(rep, att_w, att_b, temb, semb, memb, proj_w, proj_b);
    k_merged<<<2401, 256, SMEM_BYTES>>>(x, proj_w, out);
    k_fix<<<MASK_NUM, 256>>>(out);
}